// round 5
// baseline (speedup 1.0000x reference)
#include <cuda_runtime.h>

#define N_GAUSS 3200
#define FEAT    17
#define FV4     5             // padded feature float4 count (20 floats)
#define RH      48
#define RW      88
#define NPIX    (RH*RW)       // 4224
#define NPAIR   (NPIX/2)      // 2112
#define NCAM    2
#define GH      192
#define GW      352
#define NSEG    25
#define SEGSZ   128           // 25*128 = 3200
#define KCH     4
#define KLEN    (N_GAUSS/KCH) // 800
#define NTILES  (NPIX/128)    // 33 (k_loss tiling)
#define RTILES  17            // ceil(NPAIR/128) render tiling (2 px/thread)
#define NPAIRCH 9             // ceil(FEAT+1)/2 feature-channel pairs

// -------- device scratch (static: allocation-free) --------
__device__ float  d_z  [NCAM*N_GAUSS];
__device__ int    d_rank[NCAM*N_GAUSS];
__device__ float4 d_tp0[NCAM*N_GAUSS];   // unsorted u,v,A,B
__device__ float2 d_tp1[NCAM*N_GAUSS];   // unsorted C,op
__device__ float4 d_sp0[NCAM*N_GAUSS];   // sorted
__device__ float2 d_sp1[NCAM*N_GAUSS];
__device__ float4 d_sf4[NCAM*NSEG*FV4*SEGSZ]; // sorted feats, seg-blocked
__device__ float  d_segT[NCAM*NSEG*NPIX];
__device__ float  d_segA[NCAM*NSEG*FEAT*NPIX];
__device__ float  d_num[NCAM];
__device__ float  d_den[NCAM];
__device__ unsigned int d_ctr;

// -------- 1) per-gaussian projection + cov2d inverse (R1 math, packed layout) --------
__global__ void k_pre(const float* __restrict__ xyz, const float* __restrict__ scales,
                      const float* __restrict__ rots, const float* __restrict__ opac,
                      const float* __restrict__ vm, const float* __restrict__ intr)
{
    int n   = blockIdx.x * blockDim.x + threadIdx.x;
    int cam = blockIdx.y;
    if (cam == 0 && blockIdx.x == 0 && threadIdx.x < NCAM) {
        d_num[threadIdx.x] = 0.f; d_den[threadIdx.x] = 0.f;
        if (threadIdx.x == 0) d_ctr = 0u;
    }
    if (n >= N_GAUSS) return;
    d_rank[cam*N_GAUSS + n] = 0;

    const float* V = vm + cam*16;
    float fx = intr[cam*4+0], fy = intr[cam*4+1], cx = intr[cam*4+2], cy = intr[cam*4+3];
    float X = xyz[3*n], Y = xyz[3*n+1], Z = xyz[3*n+2];
    float p0 = V[0]*X + V[1]*Y + V[2] *Z + V[3];
    float p1 = V[4]*X + V[5]*Y + V[6] *Z + V[7];
    float p2 = V[8]*X + V[9]*Y + V[10]*Z + V[11];
    float z  = p2;
    float zc = fmaxf(z, 0.2f);
    float iz = 1.0f / zc;
    float u  = fx*p0*iz + cx;
    float v  = fy*p1*iz + cy;

    float qw = rots[4*n], qx = rots[4*n+1], qy = rots[4*n+2], qz = rots[4*n+3];
    float qn = rsqrtf(qw*qw + qx*qx + qy*qy + qz*qz);
    qw *= qn; qx *= qn; qy *= qn; qz *= qn;
    float R00 = 1.f-2.f*(qy*qy+qz*qz), R01 = 2.f*(qx*qy-qw*qz), R02 = 2.f*(qx*qz+qw*qy);
    float R10 = 2.f*(qx*qy+qw*qz),     R11 = 1.f-2.f*(qx*qx+qz*qz), R12 = 2.f*(qy*qz-qw*qx);
    float R20 = 2.f*(qx*qz-qw*qy),     R21 = 2.f*(qy*qz+qw*qx), R22 = 1.f-2.f*(qx*qx+qy*qy);

    float s0 = __expf(scales[3*n]), s1 = __expf(scales[3*n+1]), s2 = __expf(scales[3*n+2]);
    float e0 = s0*s0, e1 = s1*s1, e2 = s2*s2;

    float M00 = R00*R00*e0 + R01*R01*e1 + R02*R02*e2;
    float M01 = R00*R10*e0 + R01*R11*e1 + R02*R12*e2;
    float M02 = R00*R20*e0 + R01*R21*e1 + R02*R22*e2;
    float M11 = R10*R10*e0 + R11*R11*e1 + R12*R12*e2;
    float M12 = R10*R20*e0 + R11*R21*e1 + R12*R22*e2;
    float M22 = R20*R20*e0 + R21*R21*e1 + R22*R22*e2;

    float W00=V[0],W01=V[1],W02=V[2];
    float W10=V[4],W11=V[5],W12=V[6];
    float W20=V[8],W21=V[9],W22=V[10];
    float T00=W00*M00+W01*M01+W02*M02, T01=W00*M01+W01*M11+W02*M12, T02=W00*M02+W01*M12+W02*M22;
    float T10=W10*M00+W11*M01+W12*M02, T11=W10*M01+W11*M11+W12*M12, T12=W10*M02+W11*M12+W12*M22;
    float T20=W20*M00+W21*M01+W22*M02, T21=W20*M01+W21*M11+W22*M12, T22=W20*M02+W21*M12+W22*M22;
    float C00=T00*W00+T01*W01+T02*W02;
    float C01=T00*W10+T01*W11+T02*W12;
    float C02=T00*W20+T01*W21+T02*W22;
    float C11=T10*W10+T11*W11+T12*W12;
    float C12=T10*W20+T11*W21+T12*W22;
    float C22=T20*W20+T21*W21+T22*W22;

    float fz0 = fx*iz, fz1 = fy*iz;
    float g0 = -fx*p0*iz*iz, g1 = -fy*p1*iz*iz;
    float t0x = C00*fz0 + C02*g0;
    float t0y = C01*fz0 + C12*g0;
    float t0z = C02*fz0 + C22*g0;
    float cov00 = fz0*t0x + g0*t0z;
    float cov01 = fz1*t0y + g1*t0z;
    float t1y = C11*fz1 + C12*g1;
    float t1z = C12*fz1 + C22*g1;
    float cov11 = fz1*t1y + g1*t1z;

    float a = cov00 + 0.3f;
    float b = cov01;
    float c = cov11 + 0.3f;
    float det  = fmaxf(a*c - b*b, 1e-8f);
    float idet = 1.0f / det;

    float oz = (z > 0.2f) ? opac[n] : 0.0f;
    int gi = cam*N_GAUSS + n;
    d_z  [gi] = z;
    d_tp0[gi] = make_float4(u, v, c*idet, -b*idet);   // u, v, A, B (R1 values)
    d_tp1[gi] = make_float2(a*idet, oz);              // C, op
}

// -------- 2) stable argsort via O(N^2) rank counting (R3-identical) --------
__global__ void k_rank()
{
    int cam = blockIdx.z;
    int n   = blockIdx.x * 256 + threadIdx.x;
    int base = blockIdx.y * KLEN;
    __shared__ float tz[256];
    float zn = (n < N_GAUSS) ? d_z[cam*N_GAUSS + n] : 0.f;
    int cnt = 0;
    for (int t0 = 0; t0 < KLEN; t0 += 256) {
        int lim = KLEN - t0 < 256 ? KLEN - t0 : 256;
        __syncthreads();
        if (threadIdx.x < lim) tz[threadIdx.x] = d_z[cam*N_GAUSS + base + t0 + threadIdx.x];
        __syncthreads();
        if (n < N_GAUSS) {
            for (int j = 0; j < lim; j++) {
                float zm = tz[j];
                int mm = base + t0 + j;
                cnt += (zm < zn) || (zm == zn && mm < n);
            }
        }
    }
    if (n < N_GAUSS && cnt) atomicAdd(&d_rank[cam*N_GAUSS + n], cnt);
}

// -------- 3) scatter packed params + seg-blocked features (R3-identical) --------
__global__ void k_scatter(const float* __restrict__ feats)
{
    int n = blockIdx.x * 256 + threadIdx.x;
    int cam = blockIdx.y;
    if (n >= N_GAUSS) return;
    int gi   = cam*N_GAUSS + n;
    int rank = d_rank[gi];
    int pos  = cam*N_GAUSS + rank;
    d_sp0[pos] = d_tp0[gi];
    d_sp1[pos] = d_tp1[gi];
    int seg = rank / SEGSZ, t = rank % SEGSZ;
    const float* f = feats + n*FEAT;
    float fv[FV4*4];
#pragma unroll
    for (int c = 0; c < FEAT; c++) fv[c] = f[c];
#pragma unroll
    for (int c = FEAT; c < FV4*4; c++) fv[c] = 0.f;
    float4* dst = &d_sf4[((cam*NSEG + seg)*FV4)*SEGSZ + t];
#pragma unroll
    for (int j = 0; j < FV4; j++)
        dst[j*SEGSZ] = make_float4(fv[4*j], fv[4*j+1], fv[4*j+2], fv[4*j+3]);
}

// -------- 4) segmented compositing: 2 px/thread + FFMA2 pairs --------
__global__ void __launch_bounds__(128) k_render()
{
    int seg  = blockIdx.x;
    int tile = blockIdx.y;
    int cam  = blockIdx.z;
    __shared__ float4 sp0[SEGSZ];
    __shared__ float2 sp1[SEGSZ];
    __shared__ ulonglong2 sfp[NPAIRCH*SEGSZ];  // features duplicated as (f,f) pairs
    int t = threadIdx.x;
    int g = cam*N_GAUSS + seg*SEGSZ + t;
    sp0[t] = d_sp0[g];
    sp1[t] = d_sp1[g];
    {
        const float4* src = &d_sf4[((cam*NSEG + seg)*FV4)*SEGSZ + t];
        float f[FV4*4];
#pragma unroll
        for (int j = 0; j < FV4; j++) {
            float4 q = src[j*SEGSZ];
            f[4*j] = q.x; f[4*j+1] = q.y; f[4*j+2] = q.z; f[4*j+3] = q.w;
        }
#pragma unroll
        for (int j = 0; j < NPAIRCH; j++) {
            ulonglong2 e;
            asm("mov.b64 %0, {%1, %1};" : "=l"(e.x) : "f"(f[2*j]));
            asm("mov.b64 %0, {%1, %1};" : "=l"(e.y) : "f"(f[2*j+1]));
            sfp[j*SEGSZ + t] = e;
        }
    }
    __syncthreads();

    int pairIdx = tile*128 + t;
    bool valid = pairIdx < NPAIR;
    int p0 = (valid ? pairIdx : 0) * 2;
    float px0 = (float)(p0 % RW);
    float px1 = px0 + 1.0f;          // same row always (RW even, p0 even)
    float py  = (float)(p0 / RW);
    float T0 = 1.0f, T1 = 1.0f;
    unsigned long long acc2[FEAT+1];
#pragma unroll
    for (int c = 0; c < FEAT+1; c++) acc2[c] = 0ull;   // (0.f,0.f)

    for (int i = 0; i < SEGSZ; i++) {
        float4 P = sp0[i];
        float2 Q = sp1[i];
        float dy  = py - P.y;
        float dx0 = px0 - P.x;
        float dx1 = px1 - P.x;
        float pw0 = -0.5f*(P.z*dx0*dx0 + Q.x*dy*dy) - P.w*dx0*dy;  // R1 expression
        float pw1 = -0.5f*(P.z*dx1*dx1 + Q.x*dy*dy) - P.w*dx1*dy;
        pw0 = fminf(pw0, 0.0f);
        pw1 = fminf(pw1, 0.0f);
        bool s0 = pw0 > -20.0f;
        bool s1 = pw1 > -20.0f;
        if (s0 | s1) {
            float a0 = fminf(Q.y * __expf(pw0), 0.99f);
            float a1 = fminf(Q.y * __expf(pw1), 0.99f);
            float w0 = s0 ? a0 * T0 : 0.0f;
            float w1 = s1 ? a1 * T1 : 0.0f;
            unsigned long long W;
            asm("mov.b64 %0, {%1, %2};" : "=l"(W) : "f"(w0), "f"(w1));
#pragma unroll
            for (int j = 0; j < NPAIRCH; j++) {
                ulonglong2 v = sfp[j*SEGSZ + i];
                asm("fma.rn.f32x2 %0, %1, %2, %0;" : "+l"(acc2[2*j])   : "l"(W), "l"(v.x));
                asm("fma.rn.f32x2 %0, %1, %2, %0;" : "+l"(acc2[2*j+1]) : "l"(W), "l"(v.y));
            }
            if (s0) T0 *= 1.0f - a0;
            if (s1) T1 *= 1.0f - a1;
        }
    }
    if (valid) {
        int idx = cam*NSEG + seg;
        *(float2*)&d_segT[idx*NPIX + p0] = make_float2(T0, T1);
#pragma unroll
        for (int c = 0; c < FEAT; c++) {
            float lo, hi;
            asm("mov.b64 {%0, %1}, %2;" : "=f"(lo), "=f"(hi) : "l"(acc2[c]));
            *(float2*)&d_segA[(idx*FEAT + c)*NPIX + p0] = make_float2(lo, hi);
        }
    }
}

// -------- 5) combine segments + masked weighted CE + fused finalize --------
__global__ void __launch_bounds__(128) k_loss(const int* __restrict__ gt, const int* __restrict__ mk,
                                              const float* __restrict__ cw, float* __restrict__ out)
{
    int cam = blockIdx.y;
    int p = blockIdx.x*128 + threadIdx.x;
    float T = 1.0f;
    float logits[FEAT];
#pragma unroll
    for (int c = 0; c < FEAT; c++) logits[c] = 0.f;
    for (int s = 0; s < NSEG; s++) {
        int idx = cam*NSEG + s;
#pragma unroll
        for (int c = 0; c < FEAT; c++)
            logits[c] = fmaf(T, d_segA[(idx*FEAT + c)*NPIX + p], logits[c]);
        T *= d_segT[idx*NPIX + p];
    }
    int x = p % RW, y = p / RW;
    int gi = cam*GH*GW + (y*4)*GW + (x*4);
    int g = gt[gi];
    float m = (float)mk[gi];

    float mx = logits[0];
#pragma unroll
    for (int c = 1; c < FEAT; c++) mx = fmaxf(mx, logits[c]);
    float se = 0.f;
#pragma unroll
    for (int c = 0; c < FEAT; c++) se += __expf(logits[c] - mx);
    float lg = logits[0];
#pragma unroll
    for (int c = 1; c < FEAT; c++) if (c == g) lg = logits[c];
    float nll = -(lg - mx - __logf(se));
    float wi  = cw[g] * m;

    __shared__ float rn[128], rd[128];
    int t = threadIdx.x;
    rn[t] = wi * nll; rd[t] = wi;
    __syncthreads();
    for (int s = 64; s > 0; s >>= 1) {
        if (t < s) { rn[t] += rn[t+s]; rd[t] += rd[t+s]; }
        __syncthreads();
    }
    if (t == 0) {
        atomicAdd(&d_num[cam], rn[0]);
        atomicAdd(&d_den[cam], rd[0]);
        __threadfence();
        unsigned int done = atomicAdd(&d_ctr, 1u);
        if (done == NTILES*NCAM - 1) {
            float n0 = atomicAdd(&d_num[0], 0.0f), d0 = atomicAdd(&d_den[0], 0.0f);
            float n1 = atomicAdd(&d_num[1], 0.0f), d1 = atomicAdd(&d_den[1], 0.0f);
            float l0 = n0 / fmaxf(d0, 1e-8f);
            float l1 = n1 / fmaxf(d1, 1e-8f);
            out[0] = 0.5f * (l0 + l1);
        }
    }
}

extern "C" void kernel_launch(void* const* d_in, const int* in_sizes, int n_in,
                              void* d_out, int out_size)
{
    const float* vf  = (const float*)d_in[0];
    const float* op  = (const float*)d_in[1];
    const float* xyz = (const float*)d_in[2];
    const float* sc  = (const float*)d_in[3];
    const float* rt  = (const float*)d_in[4];
    const float* vm  = (const float*)d_in[5];
    const float* in_ = (const float*)d_in[6];
    const float* cw  = (const float*)d_in[7];
    const int*   gt  = (const int*)  d_in[8];
    const int*   mk  = (const int*)  d_in[9];
    float* out = (float*)d_out;

    k_pre    <<<dim3(13, NCAM), 256>>>(xyz, sc, rt, op, vm, in_);
    k_rank   <<<dim3(13, KCH, NCAM), 256>>>();
    k_scatter<<<dim3(13, NCAM), 256>>>(vf);
    k_render <<<dim3(NSEG, RTILES, NCAM), 128>>>();
    k_loss   <<<dim3(NTILES, NCAM), 128>>>(gt, mk, cw, out);
}

// round 7
// speedup vs baseline: 1.0554x; 1.0554x over previous
#include <cuda_runtime.h>

#define N_GAUSS 3200
#define FEAT    17
#define FV4     5             // padded feature float4 count (20 floats)
#define RH      48
#define RW      88
#define NPIX    (RH*RW)       // 4224
#define NPAIR   (NPIX/2)      // 2112
#define NCAM    2
#define GH      192
#define GW      352
#define NSEG    50
#define SEGSZ   64            // 50*64 = 3200
#define KCH     4
#define KLEN    (N_GAUSS/KCH) // 800
#define NTILES  (NPIX/128)    // 33 (k_loss tiling)
#define RTILES  17            // ceil(NPAIR/128) render tiling (2 px/thread)
#define NPAIRCH 9             // (FEAT+1)/2 feature-channel pairs
#define HSEG    (NSEG/2)      // 25, k_loss per-thread half

// -------- device scratch (static: allocation-free) --------
__device__ float  d_z  [NCAM*N_GAUSS];
__device__ int    d_rank[NCAM*N_GAUSS];
__device__ float4 d_tp0[NCAM*N_GAUSS];   // unsorted u,v,A,B
__device__ float2 d_tp1[NCAM*N_GAUSS];   // unsorted C,op
__device__ float4 d_sp0[NCAM*N_GAUSS];   // sorted
__device__ float2 d_sp1[NCAM*N_GAUSS];
__device__ float4 d_sf4[NCAM*NSEG*FV4*SEGSZ]; // sorted feats, seg-blocked
__device__ float  d_segT[NCAM*NSEG*NPIX];
__device__ float  d_segA[NCAM*NSEG*FEAT*NPIX];
__device__ float  d_num[NCAM];
__device__ float  d_den[NCAM];
__device__ unsigned int d_ctr;

// -------- 1) per-gaussian projection + cov2d inverse (R1 math, packed layout) --------
__global__ void k_pre(const float* __restrict__ xyz, const float* __restrict__ scales,
                      const float* __restrict__ rots, const float* __restrict__ opac,
                      const float* __restrict__ vm, const float* __restrict__ intr)
{
    int n   = blockIdx.x * blockDim.x + threadIdx.x;
    int cam = blockIdx.y;
    if (cam == 0 && blockIdx.x == 0 && threadIdx.x < NCAM) {
        d_num[threadIdx.x] = 0.f; d_den[threadIdx.x] = 0.f;
        if (threadIdx.x == 0) d_ctr = 0u;
    }
    if (n >= N_GAUSS) return;
    d_rank[cam*N_GAUSS + n] = 0;

    const float* V = vm + cam*16;
    float fx = intr[cam*4+0], fy = intr[cam*4+1], cx = intr[cam*4+2], cy = intr[cam*4+3];
    float X = xyz[3*n], Y = xyz[3*n+1], Z = xyz[3*n+2];
    float p0 = V[0]*X + V[1]*Y + V[2] *Z + V[3];
    float p1 = V[4]*X + V[5]*Y + V[6] *Z + V[7];
    float p2 = V[8]*X + V[9]*Y + V[10]*Z + V[11];
    float z  = p2;
    float zc = fmaxf(z, 0.2f);
    float iz = 1.0f / zc;
    float u  = fx*p0*iz + cx;
    float v  = fy*p1*iz + cy;

    float qw = rots[4*n], qx = rots[4*n+1], qy = rots[4*n+2], qz = rots[4*n+3];
    float qn = rsqrtf(qw*qw + qx*qx + qy*qy + qz*qz);
    qw *= qn; qx *= qn; qy *= qn; qz *= qn;
    float R00 = 1.f-2.f*(qy*qy+qz*qz), R01 = 2.f*(qx*qy-qw*qz), R02 = 2.f*(qx*qz+qw*qy);
    float R10 = 2.f*(qx*qy+qw*qz),     R11 = 1.f-2.f*(qx*qx+qz*qz), R12 = 2.f*(qy*qz-qw*qx);
    float R20 = 2.f*(qx*qz-qw*qy),     R21 = 2.f*(qy*qz+qw*qx), R22 = 1.f-2.f*(qx*qx+qy*qy);

    float s0 = __expf(scales[3*n]), s1 = __expf(scales[3*n+1]), s2 = __expf(scales[3*n+2]);
    float e0 = s0*s0, e1 = s1*s1, e2 = s2*s2;

    float M00 = R00*R00*e0 + R01*R01*e1 + R02*R02*e2;
    float M01 = R00*R10*e0 + R01*R11*e1 + R02*R12*e2;
    float M02 = R00*R20*e0 + R01*R21*e1 + R02*R22*e2;
    float M11 = R10*R10*e0 + R11*R11*e1 + R12*R12*e2;
    float M12 = R10*R20*e0 + R11*R21*e1 + R12*R22*e2;
    float M22 = R20*R20*e0 + R21*R21*e1 + R22*R22*e2;

    float W00=V[0],W01=V[1],W02=V[2];
    float W10=V[4],W11=V[5],W12=V[6];
    float W20=V[8],W21=V[9],W22=V[10];
    float T00=W00*M00+W01*M01+W02*M02, T01=W00*M01+W01*M11+W02*M12, T02=W00*M02+W01*M12+W02*M22;
    float T10=W10*M00+W11*M01+W12*M02, T11=W10*M01+W11*M11+W12*M12, T12=W10*M02+W11*M12+W12*M22;
    float T20=W20*M00+W21*M01+W22*M02, T21=W20*M01+W21*M11+W22*M12, T22=W20*M02+W21*M12+W22*M22;
    float C00=T00*W00+T01*W01+T02*W02;
    float C01=T00*W10+T01*W11+T02*W12;
    float C02=T00*W20+T01*W21+T02*W22;
    float C11=T10*W10+T11*W11+T12*W12;
    float C12=T10*W20+T11*W21+T12*W22;
    float C22=T20*W20+T21*W21+T22*W22;

    float fz0 = fx*iz, fz1 = fy*iz;
    float g0 = -fx*p0*iz*iz, g1 = -fy*p1*iz*iz;
    float t0x = C00*fz0 + C02*g0;
    float t0y = C01*fz0 + C12*g0;
    float t0z = C02*fz0 + C22*g0;
    float cov00 = fz0*t0x + g0*t0z;
    float cov01 = fz1*t0y + g1*t0z;
    float t1y = C11*fz1 + C12*g1;
    float t1z = C12*fz1 + C22*g1;
    float cov11 = fz1*t1y + g1*t1z;

    float a = cov00 + 0.3f;
    float b = cov01;
    float c = cov11 + 0.3f;
    float det  = fmaxf(a*c - b*b, 1e-8f);
    float idet = 1.0f / det;

    float oz = (z > 0.2f) ? opac[n] : 0.0f;
    int gi = cam*N_GAUSS + n;
    d_z  [gi] = z;
    d_tp0[gi] = make_float4(u, v, c*idet, -b*idet);   // u, v, A, B (R1 values)
    d_tp1[gi] = make_float2(a*idet, oz);              // C, op
}

// -------- 2) stable argsort via O(N^2) rank counting --------
__global__ void k_rank()
{
    int cam = blockIdx.z;
    int n   = blockIdx.x * 256 + threadIdx.x;
    int base = blockIdx.y * KLEN;
    __shared__ float tz[256];
    float zn = (n < N_GAUSS) ? d_z[cam*N_GAUSS + n] : 0.f;
    int cnt = 0;
    for (int t0 = 0; t0 < KLEN; t0 += 256) {
        int lim = KLEN - t0 < 256 ? KLEN - t0 : 256;
        __syncthreads();
        if (threadIdx.x < lim) tz[threadIdx.x] = d_z[cam*N_GAUSS + base + t0 + threadIdx.x];
        __syncthreads();
        if (n < N_GAUSS) {
            for (int j = 0; j < lim; j++) {
                float zm = tz[j];
                int mm = base + t0 + j;
                cnt += (zm < zn) || (zm == zn && mm < n);
            }
        }
    }
    if (n < N_GAUSS && cnt) atomicAdd(&d_rank[cam*N_GAUSS + n], cnt);
}

// -------- 3) scatter packed params + seg-blocked features --------
__global__ void k_scatter(const float* __restrict__ feats)
{
    int n = blockIdx.x * 256 + threadIdx.x;
    int cam = blockIdx.y;
    if (n >= N_GAUSS) return;
    int gi   = cam*N_GAUSS + n;
    int rank = d_rank[gi];
    int pos  = cam*N_GAUSS + rank;
    d_sp0[pos] = d_tp0[gi];
    d_sp1[pos] = d_tp1[gi];
    int seg = rank / SEGSZ, t = rank % SEGSZ;
    const float* f = feats + n*FEAT;
    float fv[FV4*4];
#pragma unroll
    for (int c = 0; c < FEAT; c++) fv[c] = f[c];
#pragma unroll
    for (int c = FEAT; c < FV4*4; c++) fv[c] = 0.f;
    float4* dst = &d_sf4[((cam*NSEG + seg)*FV4)*SEGSZ + t];
#pragma unroll
    for (int j = 0; j < FV4; j++)
        dst[j*SEGSZ] = make_float4(fv[4*j], fv[4*j+1], fv[4*j+2], fv[4*j+3]);
}

// -------- 4) segmented compositing: 2 px/thread + FFMA2, SEGSZ=64 --------
__global__ void __launch_bounds__(128) k_render()
{
    int seg  = blockIdx.x;
    int tile = blockIdx.y;
    int cam  = blockIdx.z;
    __shared__ float4 sp0[SEGSZ];
    __shared__ float2 sp1[SEGSZ];
    __shared__ ulonglong2 sfp[NPAIRCH*SEGSZ];  // features duplicated as (f,f) pairs
    int t = threadIdx.x;
    if (t < SEGSZ) {
        int g = cam*N_GAUSS + seg*SEGSZ + t;
        sp0[t] = d_sp0[g];
        sp1[t] = d_sp1[g];
        const float4* src = &d_sf4[((cam*NSEG + seg)*FV4)*SEGSZ + t];
        float f[FV4*4];
#pragma unroll
        for (int j = 0; j < FV4; j++) {
            float4 q = src[j*SEGSZ];
            f[4*j] = q.x; f[4*j+1] = q.y; f[4*j+2] = q.z; f[4*j+3] = q.w;
        }
#pragma unroll
        for (int j = 0; j < NPAIRCH; j++) {
            ulonglong2 e;
            asm("mov.b64 %0, {%1, %1};" : "=l"(e.x) : "f"(f[2*j]));
            asm("mov.b64 %0, {%1, %1};" : "=l"(e.y) : "f"(f[2*j+1]));
            sfp[j*SEGSZ + t] = e;
        }
    }
    __syncthreads();

    int pairIdx = tile*128 + t;
    bool valid = pairIdx < NPAIR;
    int p0 = (valid ? pairIdx : 0) * 2;
    float px0 = (float)(p0 % RW);
    float px1 = px0 + 1.0f;          // same row always (RW even, p0 even)
    float py  = (float)(p0 / RW);
    float T0 = 1.0f, T1 = 1.0f;
    unsigned long long acc2[FEAT+1];
#pragma unroll
    for (int c = 0; c < FEAT+1; c++) acc2[c] = 0ull;   // (0.f,0.f)

    for (int i = 0; i < SEGSZ; i++) {
        float4 P = sp0[i];
        float2 Q = sp1[i];
        float dy  = py - P.y;
        float dx0 = px0 - P.x;
        float dx1 = px1 - P.x;
        float pw0 = -0.5f*(P.z*dx0*dx0 + Q.x*dy*dy) - P.w*dx0*dy;  // R1 expression
        float pw1 = -0.5f*(P.z*dx1*dx1 + Q.x*dy*dy) - P.w*dx1*dy;
        pw0 = fminf(pw0, 0.0f);
        pw1 = fminf(pw1, 0.0f);
        bool s0 = pw0 > -20.0f;
        bool s1 = pw1 > -20.0f;
        if (s0 | s1) {
            float a0 = fminf(Q.y * __expf(pw0), 0.99f);
            float a1 = fminf(Q.y * __expf(pw1), 0.99f);
            float w0 = s0 ? a0 * T0 : 0.0f;
            float w1 = s1 ? a1 * T1 : 0.0f;
            unsigned long long W;
            asm("mov.b64 %0, {%1, %2};" : "=l"(W) : "f"(w0), "f"(w1));
#pragma unroll
            for (int j = 0; j < NPAIRCH; j++) {
                ulonglong2 v = sfp[j*SEGSZ + i];
                asm("fma.rn.f32x2 %0, %1, %2, %0;" : "+l"(acc2[2*j])   : "l"(W), "l"(v.x));
                asm("fma.rn.f32x2 %0, %1, %2, %0;" : "+l"(acc2[2*j+1]) : "l"(W), "l"(v.y));
            }
            if (s0) T0 *= 1.0f - a0;
            if (s1) T1 *= 1.0f - a1;
        }
    }
    if (valid) {
        int idx = cam*NSEG + seg;
        *(float2*)&d_segT[idx*NPIX + p0] = make_float2(T0, T1);
#pragma unroll
        for (int c = 0; c < FEAT; c++) {
            float lo, hi;
            asm("mov.b64 {%0, %1}, %2;" : "=f"(lo), "=f"(hi) : "l"(acc2[c]));
            *(float2*)&d_segA[(idx*FEAT + c)*NPIX + p0] = make_float2(lo, hi);
        }
    }
}

// -------- 5) combine (2 threads/pixel) + masked weighted CE + fused finalize --------
__global__ void __launch_bounds__(256) k_loss(const int* __restrict__ gt, const int* __restrict__ mk,
                                              const float* __restrict__ cw, float* __restrict__ out)
{
    int cam  = blockIdx.y;
    int t    = threadIdx.x;
    int lane = t & 127;               // pixel slot within tile
    int half = t >> 7;                // 0: segs [0,25), 1: segs [25,50)
    int p    = blockIdx.x*128 + lane;

    float T = 1.0f;
    float logits[FEAT];
#pragma unroll
    for (int c = 0; c < FEAT; c++) logits[c] = 0.f;
    int s0 = half * HSEG;
    for (int s = s0; s < s0 + HSEG; s++) {
        int idx = cam*NSEG + s;
#pragma unroll
        for (int c = 0; c < FEAT; c++)
            logits[c] = fmaf(T, d_segA[(idx*FEAT + c)*NPIX + p], logits[c]);
        T *= d_segT[idx*NPIX + p];
    }

    __shared__ float shf[128*FEAT];
    if (half == 1) {
#pragma unroll
        for (int c = 0; c < FEAT; c++) shf[c*128 + lane] = logits[c];
    }
    __syncthreads();

    __shared__ float rn[128], rd[128];
    if (half == 0) {
#pragma unroll
        for (int c = 0; c < FEAT; c++)
            logits[c] = fmaf(T, shf[c*128 + lane], logits[c]);

        int x = p % RW, y = p / RW;
        int gi = cam*GH*GW + (y*4)*GW + (x*4);
        int g = gt[gi];
        float m = (float)mk[gi];

        float mx = logits[0];
#pragma unroll
        for (int c = 1; c < FEAT; c++) mx = fmaxf(mx, logits[c]);
        float se = 0.f;
#pragma unroll
        for (int c = 0; c < FEAT; c++) se += __expf(logits[c] - mx);
        float lg = logits[0];
#pragma unroll
        for (int c = 1; c < FEAT; c++) if (c == g) lg = logits[c];
        float nll = -(lg - mx - __logf(se));
        float wi  = cw[g] * m;
        rn[lane] = wi * nll; rd[lane] = wi;
    }
    __syncthreads();
    for (int s = 64; s > 0; s >>= 1) {
        if (t < s) { rn[t] += rn[t+s]; rd[t] += rd[t+s]; }
        __syncthreads();
    }
    if (t == 0) {
        atomicAdd(&d_num[cam], rn[0]);
        atomicAdd(&d_den[cam], rd[0]);
        __threadfence();
        unsigned int done = atomicAdd(&d_ctr, 1u);
        if (done == NTILES*NCAM - 1) {
            float n0 = atomicAdd(&d_num[0], 0.0f), d0 = atomicAdd(&d_den[0], 0.0f);
            float n1 = atomicAdd(&d_num[1], 0.0f), d1 = atomicAdd(&d_den[1], 0.0f);
            float l0 = n0 / fmaxf(d0, 1e-8f);
            float l1 = n1 / fmaxf(d1, 1e-8f);
            out[0] = 0.5f * (l0 + l1);
        }
    }
}

extern "C" void kernel_launch(void* const* d_in, const int* in_sizes, int n_in,
                              void* d_out, int out_size)
{
    const float* vf  = (const float*)d_in[0];
    const float* op  = (const float*)d_in[1];
    const float* xyz = (const float*)d_in[2];
    const float* sc  = (const float*)d_in[3];
    const float* rt  = (const float*)d_in[4];
    const float* vm  = (const float*)d_in[5];
    const float* in_ = (const float*)d_in[6];
    const float* cw  = (const float*)d_in[7];
    const int*   gt  = (const int*)  d_in[8];
    const int*   mk  = (const int*)  d_in[9];
    float* out = (float*)d_out;

    k_pre    <<<dim3(13, NCAM), 256>>>(xyz, sc, rt, op, vm, in_);
    k_rank   <<<dim3(13, KCH, NCAM), 256>>>();
    k_scatter<<<dim3(13, NCAM), 256>>>(vf);
    k_render <<<dim3(NSEG, RTILES, NCAM), 128>>>();
    k_loss   <<<dim3(NTILES, NCAM), 256>>>(gt, mk, cw, out);   // FIX: 256 threads
}